// round 13
// baseline (speedup 1.0000x reference)
#include <cuda_runtime.h>
#include <cstdint>

#define NN  32
#define BB  32
#define CC  64
#define HW  1024
#define IMG (CC*HW)        // 65536 floats per batch image
#define TOT (BB*IMG)       // 2097152 floats per tensor
#define EMBD 128
#define ATT_KK 8
#define ATT_EPSF 0.01f
#define FULLM 0xffffffffu

// ----------------------------- persistent device state -----------------------------
__device__ float g_node_out[30][TOT];        // outputs of nodes 1..30 (node 0 == x)
__device__ float g_aggr[TOT];                // aggregation scratch
__device__ float d_pooledA[BB*CC];           // pooled-mean partial (rows 0-15)
__device__ float d_pooledB[BB*CC];           // pooled-mean partial (rows 16-31)
__device__ float d_ad[BB*NN];                // attention distribution (post-cut)
__device__ float d_nattn[NN*BB];             // node_attns [node][b]
__device__ float d_trans_a[NN*NN*BB];        // [t][src][b]
__device__ float d_trans_nf[NN*NN*BB];       // [t][src][b]
__device__ int   d_part[NN*BB];              // [node][b]
__device__ float d_w[NN*BB];                 // aggregation weights for next node [src][b]

// ===================================================================================
//                          host: replicate numpy default_rng(42)
// ===================================================================================
namespace rng42 {
typedef unsigned __int128 u128;
struct PCG { u128 state, inc; int has32; uint32_t cache; };

static inline u128 mult128() {
    return ((u128)2549297995355413924ULL << 64) | (u128)4865540595714422341ULL;
}
static inline void step(PCG& g) { g.state = g.state * mult128() + g.inc; }
static inline uint64_t rotr64(uint64_t v, unsigned r) {
    r &= 63u; return (v >> r) | (v << ((64u - r) & 63u));
}
static inline uint64_t next64(PCG& g) {
    step(g);
    uint64_t hi = (uint64_t)(g.state >> 64), lo = (uint64_t)g.state;
    return rotr64(hi ^ lo, (unsigned)(g.state >> 122));
}
static inline uint32_t next32(PCG& g) {
    if (g.has32) { g.has32 = 0; return g.cache; }
    uint64_t n = next64(g);
    g.has32 = 1; g.cache = (uint32_t)(n >> 32);
    return (uint32_t)n;
}
static void init(PCG& g) {
    uint32_t pool[4];
    uint32_t hc = 0x43b0d7e5u;
    #define HMIX(vv, dst) do { uint32_t v_ = (vv); v_ ^= hc; hc *= 0x931e8875u; \
                               v_ *= hc; v_ ^= v_ >> 16; dst = v_; } while (0)
    #define MIX(x, y) ({ uint32_t r_ = (uint32_t)((x) * 0xca01f9ddu - (y) * 0x4973f715u); \
                         r_ ^= r_ >> 16; r_; })
    HMIX(42u, pool[0]);
    for (int i = 1; i < 4; i++) HMIX(0u, pool[i]);
    for (int s = 0; s < 4; s++)
        for (int d = 0; d < 4; d++)
            if (s != d) { uint32_t h; HMIX(pool[s], h); pool[d] = MIX(pool[d], h); }
    #undef HMIX
    #undef MIX
    uint32_t hb = 0x8b51f9ddu, st[8];
    for (int i = 0; i < 8; i++) {
        uint32_t dv = pool[i & 3];
        dv ^= hb; hb *= 0x58f38dedu; dv *= hb; dv ^= dv >> 16;
        st[i] = dv;
    }
    uint64_t w[4];
    for (int k = 0; k < 4; k++) w[k] = (uint64_t)st[2*k] | ((uint64_t)st[2*k+1] << 32);
    u128 initstate = ((u128)w[0] << 64) | (u128)w[1];
    u128 initseq   = ((u128)w[2] << 64) | (u128)w[3];
    g.state = 0; g.inc = (initseq << 1) | (u128)1;
    step(g);
    g.state += initstate;
    step(g);
    g.has32 = 0; g.cache = 0;
}
static inline uint64_t bounded(PCG& g, uint64_t rngv) {
    if (rngv == 0) return 0;
    uint32_t rng = (uint32_t)rngv;
    uint32_t rng_excl = rng + 1u;
    uint64_t m = (uint64_t)next32(g) * (uint64_t)rng_excl;
    uint32_t leftover = (uint32_t)m;
    if (leftover < rng_excl) {
        uint32_t threshold = (uint32_t)((0xFFFFFFFFu - rng) % rng_excl);
        while (leftover < threshold) {
            m = (uint64_t)next32(g) * (uint64_t)rng_excl;
            leftover = (uint32_t)m;
        }
    }
    return m >> 32;
}
static void choice(PCG& g, int pop, int k, int* out) {
    int cnt = 0;
    for (int j = pop - k; j < pop; j++) {
        uint64_t val = bounded(g, (uint64_t)j);
        bool dup = false;
        for (int q = 0; q < cnt; q++) if ((uint64_t)out[q] == val) dup = true;
        out[cnt++] = dup ? j : (int)val;
    }
    for (int i = k - 1; i >= 1; i--) {
        int j = (int)bounded(g, (uint64_t)i);
        int t = out[i]; out[i] = out[j]; out[j] = t;
    }
}
} // namespace rng42

static void build_graph(unsigned in_mask[NN], unsigned out_mask[NN]) {
    rng42::PCG g; rng42::init(g);
    for (int i = 0; i < NN; i++) { in_mask[i] = 0u; out_mask[i] = 0u; }
    for (int i = 1; i < NN; i++) {
        in_mask[i] |= 1u << (i - 1);
        int k = (i < 3) ? i : 3;
        int pick[3];
        rng42::choice(g, i, k, pick);
        for (int q = 0; q < k; q++) in_mask[i] |= 1u << pick[q];
    }
    for (int j = 0; j < NN; j++) {
        unsigned m = in_mask[j];
        while (m) { int s = __builtin_ctz(m); m &= m - 1; out_mask[s] |= 1u << j; }
    }
}

// ===================================================================================
//                                      kernels
// ===================================================================================

__device__ __forceinline__ void fma2(unsigned long long& acc, unsigned long long v2,
                                     unsigned long long w2) {
    asm("fma.rn.f32x2 %0, %1, %2, %0;" : "+l"(acc) : "l"(v2), "l"(w2));
}

// pooled mean of x: one block per (b,c). Writes part A = full mean, part B = 0.
__global__ __launch_bounds__(128) void pool_x_kernel(const float* __restrict__ x) {
    int bc = blockIdx.x;
    int t = threadIdx.x;
    const float* p = x + (size_t)bc * HW;
    float s = 0.f;
    #pragma unroll
    for (int i = 0; i < 8; i++) s += p[t + i * 128];
    #pragma unroll
    for (int o = 16; o; o >>= 1) s += __shfl_down_sync(FULLM, s, o);
    __shared__ float red[4];
    if ((t & 31) == 0) red[t >> 5] = s;
    __syncthreads();
    if (t == 0) {
        d_pooledA[bc] = (red[0] + red[1] + red[2] + red[3]) * (1.f / 1024.f);
        d_pooledB[bc] = 0.f;
    }
}

// weighted aggregation: g_aggr (or d_out) = sum_src d_w[src][b] * node_out[src]
struct AggrP { int nsrc; int src[8]; };
__global__ __launch_bounds__(256) void aggr_kernel(AggrP p, const float* __restrict__ x,
                                                   float* __restrict__ fin, int use_fin) {
    int i = blockIdx.x * 256 + threadIdx.x;     // float4 index
    int b = i >> 14;
    float4 a = make_float4(0.f, 0.f, 0.f, 0.f);
    #pragma unroll 1
    for (int s = 0; s < p.nsrc; s++) {
        int src = p.src[s];
        float w = d_w[src * BB + b];
        const float4* sp4 = (src == 0) ? (const float4*)x
                                       : (const float4*)(&g_node_out[src - 1][0]);
        float4 v = sp4[i];
        a.x = fmaf(w, v.x, a.x); a.y = fmaf(w, v.y, a.y);
        a.z = fmaf(w, v.z, a.z); a.w = fmaf(w, v.w, a.w);
    }
    float4* o = use_fin ? (float4*)fin : (float4*)g_aggr;
    o[i] = a;
}

// 3x3 SAME conv 64->64 on g_aggr + ReLU + partial pooled mean
// block = (b, co-group of 16, y-half of 16 rows), 512 threads (1 row per thread).
// grid = 32*4*2 = 256.
__global__ __launch_bounds__(512, 2) void conv_kernel(const float* __restrict__ cw, int nid) {
    __shared__ __align__(16) float s_in[8][18][34];
    __shared__ __align__(16) float s_w[8][9][16];
    __shared__ float s_red[16][16];
    int tid = threadIdx.x;
    int tx = tid & 31, ty = tid >> 5;       // ty = 0..15 (row within half)
    int b      = blockIdx.x >> 3;
    int cobase = ((blockIdx.x >> 1) & 3) << 4;
    int half   = blockIdx.x & 1;
    int ybase  = half << 4;
    const float* inb = g_aggr + (size_t)b * IMG;

    unsigned long long acc2[8];
    #pragma unroll
    for (int q = 0; q < 8; q++) acc2[q] = 0ull;

    #pragma unroll 1
    for (int cc = 0; cc < 8; cc++) {
        int cib = cc * 8;
        // input slab with halo (rows ybase-1 .. ybase+16)
        #pragma unroll 1
        for (int idx = tid; idx < 8 * 18 * 34; idx += 512) {
            int ci = idx / 612; int rem = idx - ci * 612;
            int yy = rem / 34;  int xx = rem - yy * 34;
            int gy = ybase + yy - 1, gx = xx - 1;
            float v = 0.f;
            if ((unsigned)gy < 32u && (unsigned)gx < 32u)
                v = inb[(cib + ci) * HW + gy * 32 + gx];
            s_in[ci][yy][xx] = v;
        }
        // weights: cw layout (node, co, ci, 3, 3) -> s_w[ci][k][co]
        #pragma unroll 1
        for (int idx = tid; idx < 8 * 9 * 16; idx += 512) {
            int co = idx & 15; int r = idx >> 4;
            int ci = r / 9;    int k = r - ci * 9;
            s_w[ci][k][co] =
                cw[(((size_t)nid * 64 + (cobase + co)) * 64 + (cib + ci)) * 9 + k];
        }
        __syncthreads();
        #pragma unroll 1
        for (int ci = 0; ci < 8; ci++) {
            #pragma unroll
            for (int kk = 0; kk < 9; kk++) {
                const int ky = kk / 3, kx = kk - (kk / 3) * 3;
                const ulonglong2* wp =
                    reinterpret_cast<const ulonglong2*>(&s_w[ci][kk][0]);
                ulonglong2 wa = wp[0], wb = wp[1];
                ulonglong2 wc = wp[2], wd = wp[3];
                float v = s_in[ci][ty + ky][tx + kx];
                unsigned long long v2;
                asm("mov.b64 %0, {%1, %1};" : "=l"(v2) : "f"(v));
                fma2(acc2[0], v2, wa.x); fma2(acc2[1], v2, wa.y);
                fma2(acc2[2], v2, wb.x); fma2(acc2[3], v2, wb.y);
                fma2(acc2[4], v2, wc.x); fma2(acc2[5], v2, wc.y);
                fma2(acc2[6], v2, wd.x); fma2(acc2[7], v2, wd.y);
            }
        }
        __syncthreads();
    }

    // epilogue: ReLU + store + partial pooled sum (16 rows of this half)
    float* outb = &g_node_out[nid - 1][(size_t)b * IMG];
    int y = ybase + ty;
    float psum[16];
    #pragma unroll
    for (int q = 0; q < 8; q++) {
        float lo, hi;
        asm("mov.b64 {%0, %1}, %2;" : "=f"(lo), "=f"(hi) : "l"(acc2[q]));
        lo = fmaxf(lo, 0.f); hi = fmaxf(hi, 0.f);
        outb[(cobase + 2 * q)     * HW + y * 32 + tx] = lo;
        outb[(cobase + 2 * q + 1) * HW + y * 32 + tx] = hi;
        psum[2 * q] = lo; psum[2 * q + 1] = hi;
    }
    #pragma unroll
    for (int co = 0; co < 16; co++) {
        #pragma unroll
        for (int o = 16; o; o >>= 1)
            psum[co] += __shfl_down_sync(FULLM, psum[co], o);
    }
    if (tx == 0) {
        #pragma unroll
        for (int co = 0; co < 16; co++) s_red[ty][co] = psum[co];
    }
    __syncthreads();
    if (tid < 16) {
        float s = 0.f;
        #pragma unroll
        for (int wy = 0; wy < 16; wy++) s += s_red[wy][tid];
        float* pdst = half ? d_pooledB : d_pooledA;
        pdst[b * CC + cobase + tid] = s * (1.f / 1024.f);
    }
}

// attention + cut + bookkeeping. One WARP per batch (grid=32, block=32), lane = node.
struct SP {
    int stage, ntars, nxt;
    int tars[32];
    unsigned attn_before, attn_after;
    unsigned in_mask[NN];
};
__global__ __launch_bounds__(32) void scalar_kernel(SP p, const float* __restrict__ embs,
                                                    const float* __restrict__ W) {
    int b = blockIdx.x;
    int l = threadIdx.x;
    int stage = p.stage;
    int ntars = p.ntars;

    // pooled vector, distributed 2 per lane, broadcast via shfl
    float pc0 = d_pooledA[b * CC + l]      + d_pooledB[b * CC + l];
    float pc1 = d_pooledA[b * CC + 32 + l] + d_pooledB[b * CC + 32 + l];

    // q[e] = sum_c pooled[c] * W[c][e], lane holds e = l + {0,32,64,96}
    float q0 = 0.f, q1 = 0.f, q2 = 0.f, q3 = 0.f;
    #pragma unroll
    for (int c = 0; c < CC; c++) {
        float pv = (c < 32) ? __shfl_sync(FULLM, pc0, c)
                            : __shfl_sync(FULLM, pc1, c - 32);
        const float* wr = W + c * EMBD + l;
        q0 = fmaf(pv, wr[0],  q0);
        q1 = fmaf(pv, wr[32], q1);
        q2 = fmaf(pv, wr[64], q2);
        q3 = fmaf(pv, wr[96], q3);
    }
    // logits: lane j ends up holding lg for target j
    float lgj = 0.f;
    #pragma unroll 1
    for (int j = 0; j < ntars; j++) {
        const float* er = embs + p.tars[j] * EMBD + l;
        float s = q0 * er[0] + q1 * er[32] + q2 * er[64] + q3 * er[96];
        #pragma unroll
        for (int o = 16; o; o >>= 1) s += __shfl_down_sync(FULLM, s, o);
        s = __shfl_sync(FULLM, s, 0);
        if (l == j) lgj = s;
    }
    bool isT = (l < ntars);

    // softmax over targets (warp-parallel)
    float v = isT ? lgj : -1e30f;
    #pragma unroll
    for (int o = 16; o; o >>= 1) v = fmaxf(v, __shfl_xor_sync(FULLM, v, o));
    float e = isT ? expf(lgj - v) : 0.f;
    float den = e;
    #pragma unroll
    for (int o = 16; o; o >>= 1) den += __shfl_xor_sync(FULLM, den, o);
    float sa = 1.f, pmv = 1.f;
    if (stage > 0) {
        sa  = d_nattn[stage * BB + b];
        pmv = d_part[stage * BB + b] ? 1.f : 0.f;
    }
    float asj = isT ? (e / den) * sa * pmv : 0.f;     // a_sent[j] on lane j

    // attention distribution: lane owns t = l
    float adv;
    if (stage == 0) adv = 0.f;
    else { adv = d_ad[b * NN + l]; if (l == stage) adv = 0.f; }
    #pragma unroll 1
    for (int j = 0; j < ntars; j++) {
        float aj = __shfl_sync(FULLM, asj, j);
        if (l == p.tars[j]) adv += aj;
    }

    // top-8 (ties -> lowest index): 8 warp argmax rounds
    bool sel = false;
    #pragma unroll 1
    for (int k = 0; k < ATT_KK; k++) {
        float cv = sel ? -1e30f : adv;
        int   ci_ = l;
        #pragma unroll
        for (int o = 16; o; o >>= 1) {
            float ov = __shfl_xor_sync(FULLM, cv, o);
            int   oi = __shfl_xor_sync(FULLM, ci_, o);
            if (ov > cv || (ov == cv && oi < ci_)) { cv = ov; ci_ = oi; }
        }
        if (l == ci_) sel = true;
    }
    float mskv = (sel && adv > ATT_EPSF) ? 1.f : 0.f;
    float ssum = mskv * adv;
    #pragma unroll
    for (int o = 16; o; o >>= 1) ssum += __shfl_xor_sync(FULLM, ssum, o);
    float scale = (ssum > 0.f) ? 1.f / fmaxf(ssum, 1e-12f) : 0.f;
    d_ad[b * NN + l] = adv * mskv * scale;

    // bookkeeping
    if (stage == 0) {
        if (l == 0) d_part[0 * BB + b] = 1;
        int tt = p.tars[isT ? l : 0];
        float mt = __shfl_sync(FULLM, mskv, tt);
        if (isT) {
            float ar = asj * mt * scale;
            d_trans_a[(tt * NN + 0) * BB + b]  = ar;
            d_trans_nf[(tt * NN + 0) * BB + b] = 1.f;
            d_nattn[tt * BB + b] = ar;
        }
    } else {
        if (isT) {
            int t = p.tars[l];
            d_trans_a[(t * NN + stage) * BB + b]  = asj;
            d_trans_nf[(t * NN + stage) * BB + b] = 1.f;
            float prev = ((p.attn_before >> t) & 1u) ? d_nattn[t * BB + b] : 0.f;
            d_nattn[t * BB + b] = prev + asj;
        }
        __syncwarp();
        // renorm (lane t = l handles its own sources in parallel)
        if (l > stage && ((p.attn_after >> l) & 1u)) {
            float nf = mskv * scale;
            unsigned sm = p.in_mask[l] & ((1u << (stage + 1)) - 1u);
            while (sm) {
                int src = __ffs(sm) - 1; sm &= sm - 1;
                d_trans_nf[(l * NN + src) * BB + b] *= nf;
            }
            d_nattn[l * BB + b] *= nf;
        }
    }
    __syncwarp();
    // precompute next node's aggregation weights + part (lane = source id)
    {
        int nx = p.nxt;
        int cm = 0;
        if ((p.in_mask[nx] >> l) & 1u) {
            float tra = d_trans_a[(nx * NN + l) * BB + b] *
                        d_trans_nf[(nx * NN + l) * BB + b];
            int ps = (l == 0) ? 1 : d_part[l * BB + b];
            cm = (tra != 0.f) && ps;
            float wsrc = (l == 0) ? 1.f : d_nattn[l * BB + b];
            d_w[l * BB + b] = cm ? wsrc : 0.f;
        }
        unsigned bal = __ballot_sync(FULLM, cm);
        if (l == 0) d_part[nx * BB + b] = (bal != 0u);
    }
}

// ===================================================================================
//                                     launcher
// ===================================================================================
extern "C" void kernel_launch(void* const* d_in, const int* in_sizes, int n_in,
                              void* d_out, int out_size) {
    const float* x    = (const float*)d_in[0];
    const float* embs = (const float*)d_in[1];
    const float* w1   = (const float*)d_in[2];
    const float* w2   = (const float*)d_in[3];
    const float* cw   = (const float*)d_in[4];
    float* outp = (float*)d_out;
    (void)in_sizes; (void)n_in; (void)out_size;

    unsigned in_mask[NN], out_mask[NN];
    build_graph(in_mask, out_mask);

    pool_x_kernel<<<BB * CC, 128>>>(x);

    unsigned attn = 0u;
    // stage 0
    {
        SP sp;
        sp.stage = 0; sp.nxt = 1; sp.ntars = 0;
        unsigned m = out_mask[0];
        while (m) { int t = __builtin_ctz(m); m &= m - 1; sp.tars[sp.ntars++] = t; }
        for (int t = sp.ntars; t < 32; t++) sp.tars[t] = 0;
        sp.attn_before = 0u; sp.attn_after = out_mask[0];
        for (int t = 0; t < NN; t++) sp.in_mask[t] = in_mask[t];
        scalar_kernel<<<BB, 32>>>(sp, embs, w1);
        attn |= out_mask[0];
    }
    for (int nid = 1; nid < NN - 1; nid++) {
        AggrP ap; ap.nsrc = 0;
        unsigned m = in_mask[nid];
        while (m) { int s = __builtin_ctz(m); m &= m - 1; ap.src[ap.nsrc++] = s; }
        for (int s = ap.nsrc; s < 8; s++) ap.src[s] = 0;
        aggr_kernel<<<TOT / 1024, 256>>>(ap, x, outp, 0);

        conv_kernel<<<BB * 8, 512>>>(cw, nid);

        SP sp;
        sp.stage = nid; sp.nxt = nid + 1; sp.ntars = 0;
        unsigned mm = out_mask[nid];
        while (mm) { int t = __builtin_ctz(mm); mm &= mm - 1; sp.tars[sp.ntars++] = t; }
        for (int t = sp.ntars; t < 32; t++) sp.tars[t] = 0;
        sp.attn_before = attn; sp.attn_after = attn | out_mask[nid];
        for (int t = 0; t < NN; t++) sp.in_mask[t] = in_mask[t];
        scalar_kernel<<<BB, 32>>>(sp, embs, w2);
        attn |= out_mask[nid];
    }
    // final node 31: aggregation only -> d_out
    {
        AggrP ap; ap.nsrc = 0;
        unsigned m = in_mask[NN - 1];
        while (m) { int s = __builtin_ctz(m); m &= m - 1; ap.src[ap.nsrc++] = s; }
        for (int s = ap.nsrc; s < 8; s++) ap.src[s] = 0;
        aggr_kernel<<<TOT / 1024, 256>>>(ap, x, outp, 1);
    }
}

// round 15
// speedup vs baseline: 1.5318x; 1.5318x over previous
#include <cuda_runtime.h>
#include <cstdint>

#define NN  32
#define BB  32
#define CC  64
#define HW  1024
#define IMG (CC*HW)        // 65536 floats per batch image
#define TOT (BB*IMG)       // 2097152 floats per tensor
#define EMBD 128
#define ATT_KK 8
#define ATT_EPSF 0.01f
#define FULLM 0xffffffffu

// ----------------------------- persistent device state -----------------------------
__device__ float g_node_out[30][TOT];        // outputs of nodes 1..30 (node 0 == x)
__device__ float g_aggr[TOT];                // aggregation scratch
__device__ float d_pooledA[BB*CC];           // pooled-mean partial (half 0)
__device__ float d_pooledB[BB*CC];           // pooled-mean partial (half 1)
__device__ float d_ad[BB*NN];                // attention distribution (post-cut)
__device__ float d_nattn[NN*BB];             // node_attns [node][b]
__device__ float d_trans_a[NN*NN*BB];        // [t][src][b]
__device__ float d_trans_nf[NN*NN*BB];       // [t][src][b]
__device__ int   d_part[NN*BB];              // [node][b]
__device__ float d_w[NN*BB];                 // aggregation weights for next node [src][b]

// ===================================================================================
//                          host: replicate numpy default_rng(42)
// ===================================================================================
namespace rng42 {
typedef unsigned __int128 u128;
struct PCG { u128 state, inc; int has32; uint32_t cache; };

static inline u128 mult128() {
    return ((u128)2549297995355413924ULL << 64) | (u128)4865540595714422341ULL;
}
static inline void step(PCG& g) { g.state = g.state * mult128() + g.inc; }
static inline uint64_t rotr64(uint64_t v, unsigned r) {
    r &= 63u; return (v >> r) | (v << ((64u - r) & 63u));
}
static inline uint64_t next64(PCG& g) {
    step(g);
    uint64_t hi = (uint64_t)(g.state >> 64), lo = (uint64_t)g.state;
    return rotr64(hi ^ lo, (unsigned)(g.state >> 122));
}
static inline uint32_t next32(PCG& g) {
    if (g.has32) { g.has32 = 0; return g.cache; }
    uint64_t n = next64(g);
    g.has32 = 1; g.cache = (uint32_t)(n >> 32);
    return (uint32_t)n;
}
static void init(PCG& g) {
    uint32_t pool[4];
    uint32_t hc = 0x43b0d7e5u;
    #define HMIX(vv, dst) do { uint32_t v_ = (vv); v_ ^= hc; hc *= 0x931e8875u; \
                               v_ *= hc; v_ ^= v_ >> 16; dst = v_; } while (0)
    #define MIX(x, y) ({ uint32_t r_ = (uint32_t)((x) * 0xca01f9ddu - (y) * 0x4973f715u); \
                         r_ ^= r_ >> 16; r_; })
    HMIX(42u, pool[0]);
    for (int i = 1; i < 4; i++) HMIX(0u, pool[i]);
    for (int s = 0; s < 4; s++)
        for (int d = 0; d < 4; d++)
            if (s != d) { uint32_t h; HMIX(pool[s], h); pool[d] = MIX(pool[d], h); }
    #undef HMIX
    #undef MIX
    uint32_t hb = 0x8b51f9ddu, st[8];
    for (int i = 0; i < 8; i++) {
        uint32_t dv = pool[i & 3];
        dv ^= hb; hb *= 0x58f38dedu; dv *= hb; dv ^= dv >> 16;
        st[i] = dv;
    }
    uint64_t w[4];
    for (int k = 0; k < 4; k++) w[k] = (uint64_t)st[2*k] | ((uint64_t)st[2*k+1] << 32);
    u128 initstate = ((u128)w[0] << 64) | (u128)w[1];
    u128 initseq   = ((u128)w[2] << 64) | (u128)w[3];
    g.state = 0; g.inc = (initseq << 1) | (u128)1;
    step(g);
    g.state += initstate;
    step(g);
    g.has32 = 0; g.cache = 0;
}
static inline uint64_t bounded(PCG& g, uint64_t rngv) {
    if (rngv == 0) return 0;
    uint32_t rng = (uint32_t)rngv;
    uint32_t rng_excl = rng + 1u;
    uint64_t m = (uint64_t)next32(g) * (uint64_t)rng_excl;
    uint32_t leftover = (uint32_t)m;
    if (leftover < rng_excl) {
        uint32_t threshold = (uint32_t)((0xFFFFFFFFu - rng) % rng_excl);
        while (leftover < threshold) {
            m = (uint64_t)next32(g) * (uint64_t)rng_excl;
            leftover = (uint32_t)m;
        }
    }
    return m >> 32;
}
static void choice(PCG& g, int pop, int k, int* out) {
    int cnt = 0;
    for (int j = pop - k; j < pop; j++) {
        uint64_t val = bounded(g, (uint64_t)j);
        bool dup = false;
        for (int q = 0; q < cnt; q++) if ((uint64_t)out[q] == val) dup = true;
        out[cnt++] = dup ? j : (int)val;
    }
    for (int i = k - 1; i >= 1; i--) {
        int j = (int)bounded(g, (uint64_t)i);
        int t = out[i]; out[i] = out[j]; out[j] = t;
    }
}
} // namespace rng42

static void build_graph(unsigned in_mask[NN], unsigned out_mask[NN]) {
    rng42::PCG g; rng42::init(g);
    for (int i = 0; i < NN; i++) { in_mask[i] = 0u; out_mask[i] = 0u; }
    for (int i = 1; i < NN; i++) {
        in_mask[i] |= 1u << (i - 1);
        int k = (i < 3) ? i : 3;
        int pick[3];
        rng42::choice(g, i, k, pick);
        for (int q = 0; q < k; q++) in_mask[i] |= 1u << pick[q];
    }
    for (int j = 0; j < NN; j++) {
        unsigned m = in_mask[j];
        while (m) { int s = __builtin_ctz(m); m &= m - 1; out_mask[s] |= 1u << j; }
    }
}

// ===================================================================================
//                                      kernels
// ===================================================================================

__device__ __forceinline__ void fma2(unsigned long long& acc, unsigned long long v2,
                                     unsigned long long w2) {
    asm("fma.rn.f32x2 %0, %1, %2, %0;" : "+l"(acc) : "l"(v2), "l"(w2));
}

// pooled mean of x: one block per (b,c). Writes part A = full mean, part B = 0.
__global__ __launch_bounds__(128) void pool_x_kernel(const float* __restrict__ x) {
    int bc = blockIdx.x;
    int t = threadIdx.x;
    const float* p = x + (size_t)bc * HW;
    float s = 0.f;
    #pragma unroll
    for (int i = 0; i < 8; i++) s += p[t + i * 128];
    #pragma unroll
    for (int o = 16; o; o >>= 1) s += __shfl_down_sync(FULLM, s, o);
    __shared__ float red[4];
    if ((t & 31) == 0) red[t >> 5] = s;
    __syncthreads();
    if (t == 0) {
        d_pooledA[bc] = (red[0] + red[1] + red[2] + red[3]) * (1.f / 1024.f);
        d_pooledB[bc] = 0.f;
    }
}

// weighted aggregation: g_aggr (or d_out) = sum_src d_w[src][b] * node_out[src]
struct AggrP { int nsrc; int src[8]; };
__global__ __launch_bounds__(256) void aggr_kernel(AggrP p, const float* __restrict__ x,
                                                   float* __restrict__ fin, int use_fin) {
    int i = blockIdx.x * 256 + threadIdx.x;     // float4 index
    int b = i >> 14;
    float4 a = make_float4(0.f, 0.f, 0.f, 0.f);
    #pragma unroll 1
    for (int s = 0; s < p.nsrc; s++) {
        int src = p.src[s];
        float w = d_w[src * BB + b];
        const float4* sp4 = (src == 0) ? (const float4*)x
                                       : (const float4*)(&g_node_out[src - 1][0]);
        float4 v = sp4[i];
        a.x = fmaf(w, v.x, a.x); a.y = fmaf(w, v.y, a.y);
        a.z = fmaf(w, v.z, a.z); a.w = fmaf(w, v.w, a.w);
    }
    float4* o = use_fin ? (float4*)fin : (float4*)g_aggr;
    o[i] = a;
}

// 3x3 SAME conv 64->64 on g_aggr + ReLU + partial pooled mean
// block = (b, co-group of 8, y-half of 16 rows), 256 threads / 8 warps.
// Each thread: 2 rows (ty, ty+8 of its half) x 4 co-pairs (8 co).
// grid = 32 * 8 * 2 = 512.
__global__ __launch_bounds__(256, 4) void conv_kernel(const float* __restrict__ cw, int nid) {
    __shared__ __align__(16) float s_in[8][18][34];
    __shared__ __align__(16) float s_w[8][9][8];
    __shared__ float s_red[8][8];
    int tid = threadIdx.x;
    int tx = tid & 31, ty = tid >> 5;       // ty = warp id 0..7
    int bid    = blockIdx.x;
    int b      = bid >> 4;
    int cobase = ((bid >> 1) & 7) << 3;
    int half   = bid & 1;
    int ybase  = half << 4;
    const float* inb = g_aggr + (size_t)b * IMG;

    // halo columns (x = -1 and x = 32) are always outside the image -> zero ONCE
    #pragma unroll 1
    for (int idx = tid; idx < 8 * 18; idx += 256) {
        int ci = idx / 18, r = idx - ci * 18;
        s_in[ci][r][0]  = 0.f;
        s_in[ci][r][33] = 0.f;
    }

    unsigned long long acc2[2][4];
    #pragma unroll
    for (int pz = 0; pz < 2; pz++)
        #pragma unroll
        for (int q = 0; q < 4; q++) acc2[pz][q] = 0ull;

    #pragma unroll 1
    for (int cc = 0; cc < 8; cc++) {
        int cib = cc * 8;
        // warp ty loads its ci = ty: 18 rows, fully coalesced, no div/mod
        {
            const float* src = inb + (size_t)(cib + ty) * HW;
            #pragma unroll
            for (int r = 0; r < 18; r++) {
                int gy = ybase + r - 1;
                float v = ((unsigned)gy < 32u) ? src[gy * 32 + tx] : 0.f;
                s_in[ty][r][1 + tx] = v;
            }
        }
        // weights: cw (node, co, ci, 3, 3) -> s_w[ci][k][co], 576 floats
        #pragma unroll
        for (int it = 0; it < 3; it++) {
            int idx = tid + it * 256;
            if (idx < 576) {
                int co = idx & 7; int r = idx >> 3;
                int ci = r / 9;   int k = r - ci * 9;
                s_w[ci][k][co] =
                    cw[(((size_t)nid * 64 + (cobase + co)) * 64 + (cib + ci)) * 9 + k];
            }
        }
        __syncthreads();
        #pragma unroll 1
        for (int ci = 0; ci < 8; ci++) {
            #pragma unroll
            for (int kk = 0; kk < 9; kk++) {
                const int ky = kk / 3, kx = kk - (kk / 3) * 3;
                const ulonglong2* wp =
                    reinterpret_cast<const ulonglong2*>(&s_w[ci][kk][0]);
                ulonglong2 wa = wp[0], wb = wp[1];
                #pragma unroll
                for (int pz = 0; pz < 2; pz++) {
                    float v = s_in[ci][ty + pz * 8 + ky][tx + kx];
                    unsigned long long v2;
                    asm("mov.b64 %0, {%1, %1};" : "=l"(v2) : "f"(v));
                    fma2(acc2[pz][0], v2, wa.x); fma2(acc2[pz][1], v2, wa.y);
                    fma2(acc2[pz][2], v2, wb.x); fma2(acc2[pz][3], v2, wb.y);
                }
            }
        }
        __syncthreads();
    }

    // epilogue: ReLU + store + partial pooled sum over this half's 16 rows
    float* outb = &g_node_out[nid - 1][(size_t)b * IMG];
    float psum[8];
    #pragma unroll
    for (int c = 0; c < 8; c++) psum[c] = 0.f;
    #pragma unroll
    for (int pz = 0; pz < 2; pz++) {
        int y = ybase + ty + pz * 8;
        #pragma unroll
        for (int q = 0; q < 4; q++) {
            float lo, hi;
            asm("mov.b64 {%0, %1}, %2;" : "=f"(lo), "=f"(hi) : "l"(acc2[pz][q]));
            lo = fmaxf(lo, 0.f); hi = fmaxf(hi, 0.f);
            outb[(cobase + 2 * q)     * HW + y * 32 + tx] = lo;
            outb[(cobase + 2 * q + 1) * HW + y * 32 + tx] = hi;
            psum[2 * q] += lo; psum[2 * q + 1] += hi;
        }
    }
    #pragma unroll
    for (int c = 0; c < 8; c++) {
        #pragma unroll
        for (int o = 16; o; o >>= 1)
            psum[c] += __shfl_down_sync(FULLM, psum[c], o);
    }
    if (tx == 0) {
        #pragma unroll
        for (int c = 0; c < 8; c++) s_red[ty][c] = psum[c];
    }
    __syncthreads();
    if (tid < 8) {
        float s = 0.f;
        #pragma unroll
        for (int wy = 0; wy < 8; wy++) s += s_red[wy][tid];
        float* pdst = half ? d_pooledB : d_pooledA;
        pdst[b * CC + cobase + tid] = s * (1.f / 1024.f);
    }
}

// attention + cut + bookkeeping. One WARP per batch (grid=32, block=32), lane = node.
struct SP {
    int stage, ntars, nxt;
    int tars[32];
    unsigned attn_before, attn_after;
    unsigned in_mask[NN];
};
__global__ __launch_bounds__(32) void scalar_kernel(SP p, const float* __restrict__ embs,
                                                    const float* __restrict__ W) {
    int b = blockIdx.x;
    int l = threadIdx.x;
    int stage = p.stage;
    int ntars = p.ntars;

    // pooled vector, distributed 2 per lane, broadcast via shfl
    float pc0 = d_pooledA[b * CC + l]      + d_pooledB[b * CC + l];
    float pc1 = d_pooledA[b * CC + 32 + l] + d_pooledB[b * CC + 32 + l];

    // q[e] = sum_c pooled[c] * W[c][e], lane holds e = l + {0,32,64,96}
    float q0 = 0.f, q1 = 0.f, q2 = 0.f, q3 = 0.f;
    #pragma unroll
    for (int c = 0; c < CC; c++) {
        float pv = (c < 32) ? __shfl_sync(FULLM, pc0, c)
                            : __shfl_sync(FULLM, pc1, c - 32);
        const float* wr = W + c * EMBD + l;
        q0 = fmaf(pv, wr[0],  q0);
        q1 = fmaf(pv, wr[32], q1);
        q2 = fmaf(pv, wr[64], q2);
        q3 = fmaf(pv, wr[96], q3);
    }
    // logits: lane j ends up holding lg for target j
    float lgj = 0.f;
    #pragma unroll 1
    for (int j = 0; j < ntars; j++) {
        const float* er = embs + p.tars[j] * EMBD + l;
        float s = q0 * er[0] + q1 * er[32] + q2 * er[64] + q3 * er[96];
        #pragma unroll
        for (int o = 16; o; o >>= 1) s += __shfl_down_sync(FULLM, s, o);
        s = __shfl_sync(FULLM, s, 0);
        if (l == j) lgj = s;
    }
    bool isT = (l < ntars);

    // softmax over targets (warp-parallel)
    float v = isT ? lgj : -1e30f;
    #pragma unroll
    for (int o = 16; o; o >>= 1) v = fmaxf(v, __shfl_xor_sync(FULLM, v, o));
    float e = isT ? expf(lgj - v) : 0.f;
    float den = e;
    #pragma unroll
    for (int o = 16; o; o >>= 1) den += __shfl_xor_sync(FULLM, den, o);
    float sa = 1.f, pmv = 1.f;
    if (stage > 0) {
        sa  = d_nattn[stage * BB + b];
        pmv = d_part[stage * BB + b] ? 1.f : 0.f;
    }
    float asj = isT ? (e / den) * sa * pmv : 0.f;     // a_sent[j] on lane j

    // attention distribution: lane owns t = l
    float adv;
    if (stage == 0) adv = 0.f;
    else { adv = d_ad[b * NN + l]; if (l == stage) adv = 0.f; }
    #pragma unroll 1
    for (int j = 0; j < ntars; j++) {
        float aj = __shfl_sync(FULLM, asj, j);
        if (l == p.tars[j]) adv += aj;
    }

    // top-8 (ties -> lowest index): 8 warp argmax rounds
    bool sel = false;
    #pragma unroll 1
    for (int k = 0; k < ATT_KK; k++) {
        float cv = sel ? -1e30f : adv;
        int   ci_ = l;
        #pragma unroll
        for (int o = 16; o; o >>= 1) {
            float ov = __shfl_xor_sync(FULLM, cv, o);
            int   oi = __shfl_xor_sync(FULLM, ci_, o);
            if (ov > cv || (ov == cv && oi < ci_)) { cv = ov; ci_ = oi; }
        }
        if (l == ci_) sel = true;
    }
    float mskv = (sel && adv > ATT_EPSF) ? 1.f : 0.f;
    float ssum = mskv * adv;
    #pragma unroll
    for (int o = 16; o; o >>= 1) ssum += __shfl_xor_sync(FULLM, ssum, o);
    float scale = (ssum > 0.f) ? 1.f / fmaxf(ssum, 1e-12f) : 0.f;
    d_ad[b * NN + l] = adv * mskv * scale;

    // bookkeeping
    if (stage == 0) {
        if (l == 0) d_part[0 * BB + b] = 1;
        int tt = p.tars[isT ? l : 0];
        float mt = __shfl_sync(FULLM, mskv, tt);
        if (isT) {
            float ar = asj * mt * scale;
            d_trans_a[(tt * NN + 0) * BB + b]  = ar;
            d_trans_nf[(tt * NN + 0) * BB + b] = 1.f;
            d_nattn[tt * BB + b] = ar;
        }
    } else {
        if (isT) {
            int t = p.tars[l];
            d_trans_a[(t * NN + stage) * BB + b]  = asj;
            d_trans_nf[(t * NN + stage) * BB + b] = 1.f;
            float prev = ((p.attn_before >> t) & 1u) ? d_nattn[t * BB + b] : 0.f;
            d_nattn[t * BB + b] = prev + asj;
        }
        __syncwarp();
        // renorm (lane t = l handles its own sources in parallel)
        if (l > stage && ((p.attn_after >> l) & 1u)) {
            float nf = mskv * scale;
            unsigned sm = p.in_mask[l] & ((1u << (stage + 1)) - 1u);
            while (sm) {
                int src = __ffs(sm) - 1; sm &= sm - 1;
                d_trans_nf[(l * NN + src) * BB + b] *= nf;
            }
            d_nattn[l * BB + b] *= nf;
        }
    }
    __syncwarp();
    // precompute next node's aggregation weights + part (lane = source id)
    {
        int nx = p.nxt;
        int cm = 0;
        if ((p.in_mask[nx] >> l) & 1u) {
            float tra = d_trans_a[(nx * NN + l) * BB + b] *
                        d_trans_nf[(nx * NN + l) * BB + b];
            int ps = (l == 0) ? 1 : d_part[l * BB + b];
            cm = (tra != 0.f) && ps;
            float wsrc = (l == 0) ? 1.f : d_nattn[l * BB + b];
            d_w[l * BB + b] = cm ? wsrc : 0.f;
        }
        unsigned bal = __ballot_sync(FULLM, cm);
        if (l == 0) d_part[nx * BB + b] = (bal != 0u);
    }
}

// ===================================================================================
//                                     launcher
// ===================================================================================
extern "C" void kernel_launch(void* const* d_in, const int* in_sizes, int n_in,
                              void* d_out, int out_size) {
    const float* x    = (const float*)d_in[0];
    const float* embs = (const float*)d_in[1];
    const float* w1   = (const float*)d_in[2];
    const float* w2   = (const float*)d_in[3];
    const float* cw   = (const float*)d_in[4];
    float* outp = (float*)d_out;
    (void)in_sizes; (void)n_in; (void)out_size;

    unsigned in_mask[NN], out_mask[NN];
    build_graph(in_mask, out_mask);

    pool_x_kernel<<<BB * CC, 128>>>(x);

    unsigned attn = 0u;
    // stage 0
    {
        SP sp;
        sp.stage = 0; sp.nxt = 1; sp.ntars = 0;
        unsigned m = out_mask[0];
        while (m) { int t = __builtin_ctz(m); m &= m - 1; sp.tars[sp.ntars++] = t; }
        for (int t = sp.ntars; t < 32; t++) sp.tars[t] = 0;
        sp.attn_before = 0u; sp.attn_after = out_mask[0];
        for (int t = 0; t < NN; t++) sp.in_mask[t] = in_mask[t];
        scalar_kernel<<<BB, 32>>>(sp, embs, w1);
        attn |= out_mask[0];
    }
    for (int nid = 1; nid < NN - 1; nid++) {
        AggrP ap; ap.nsrc = 0;
        unsigned m = in_mask[nid];
        while (m) { int s = __builtin_ctz(m); m &= m - 1; ap.src[ap.nsrc++] = s; }
        for (int s = ap.nsrc; s < 8; s++) ap.src[s] = 0;
        aggr_kernel<<<TOT / 1024, 256>>>(ap, x, outp, 0);

        conv_kernel<<<BB * 16, 256>>>(cw, nid);

        SP sp;
        sp.stage = nid; sp.nxt = nid + 1; sp.ntars = 0;
        unsigned mm = out_mask[nid];
        while (mm) { int t = __builtin_ctz(mm); mm &= mm - 1; sp.tars[sp.ntars++] = t; }
        for (int t = sp.ntars; t < 32; t++) sp.tars[t] = 0;
        sp.attn_before = attn; sp.attn_after = attn | out_mask[nid];
        for (int t = 0; t < NN; t++) sp.in_mask[t] = in_mask[t];
        scalar_kernel<<<BB, 32>>>(sp, embs, w2);
        attn |= out_mask[nid];
    }
    // final node 31: aggregation only -> d_out
    {
        AggrP ap; ap.nsrc = 0;
        unsigned m = in_mask[NN - 1];
        while (m) { int s = __builtin_ctz(m); m &= m - 1; ap.src[ap.nsrc++] = s; }
        for (int s = ap.nsrc; s < 8; s++) ap.src[s] = 0;
        aggr_kernel<<<TOT / 1024, 256>>>(ap, x, outp, 1);
    }
}

// round 16
// speedup vs baseline: 1.8243x; 1.1910x over previous
#include <cuda_runtime.h>
#include <cstdint>

#define NN  32
#define BB  32
#define CC  64
#define HW  1024
#define IMG (CC*HW)        // 65536 floats per batch image
#define TOT (BB*IMG)       // 2097152 floats per tensor
#define EMBD 128
#define ATT_KK 8
#define ATT_EPSF 0.01f
#define FULLM 0xffffffffu

// ----------------------------- persistent device state -----------------------------
__device__ float g_node_out[30][TOT];        // outputs of nodes 1..30 (node 0 == x)
__device__ float g_aggr[TOT];                // aggregation scratch
__device__ float d_pooled[BB*CC];            // pooled means of current node output
__device__ float d_ad[BB*NN];                // attention distribution (post-cut)
__device__ float d_nattn[NN*BB];             // node_attns [node][b]
__device__ float d_trans_a[NN*NN*BB];        // [t][src][b]
__device__ float d_trans_nf[NN*NN*BB];       // [t][src][b]
__device__ int   d_part[NN*BB];              // [node][b]
__device__ float d_w[NN*BB];                 // aggregation weights for next node [src][b]

// ===================================================================================
//                          host: replicate numpy default_rng(42)
// ===================================================================================
namespace rng42 {
typedef unsigned __int128 u128;
struct PCG { u128 state, inc; int has32; uint32_t cache; };

static inline u128 mult128() {
    return ((u128)2549297995355413924ULL << 64) | (u128)4865540595714422341ULL;
}
static inline void step(PCG& g) { g.state = g.state * mult128() + g.inc; }
static inline uint64_t rotr64(uint64_t v, unsigned r) {
    r &= 63u; return (v >> r) | (v << ((64u - r) & 63u));
}
static inline uint64_t next64(PCG& g) {
    step(g);
    uint64_t hi = (uint64_t)(g.state >> 64), lo = (uint64_t)g.state;
    return rotr64(hi ^ lo, (unsigned)(g.state >> 122));
}
static inline uint32_t next32(PCG& g) {
    if (g.has32) { g.has32 = 0; return g.cache; }
    uint64_t n = next64(g);
    g.has32 = 1; g.cache = (uint32_t)(n >> 32);
    return (uint32_t)n;
}
static void init(PCG& g) {
    uint32_t pool[4];
    uint32_t hc = 0x43b0d7e5u;
    #define HMIX(vv, dst) do { uint32_t v_ = (vv); v_ ^= hc; hc *= 0x931e8875u; \
                               v_ *= hc; v_ ^= v_ >> 16; dst = v_; } while (0)
    #define MIX(x, y) ({ uint32_t r_ = (uint32_t)((x) * 0xca01f9ddu - (y) * 0x4973f715u); \
                         r_ ^= r_ >> 16; r_; })
    HMIX(42u, pool[0]);
    for (int i = 1; i < 4; i++) HMIX(0u, pool[i]);
    for (int s = 0; s < 4; s++)
        for (int d = 0; d < 4; d++)
            if (s != d) { uint32_t h; HMIX(pool[s], h); pool[d] = MIX(pool[d], h); }
    #undef HMIX
    #undef MIX
    uint32_t hb = 0x8b51f9ddu, st[8];
    for (int i = 0; i < 8; i++) {
        uint32_t dv = pool[i & 3];
        dv ^= hb; hb *= 0x58f38dedu; dv *= hb; dv ^= dv >> 16;
        st[i] = dv;
    }
    uint64_t w[4];
    for (int k = 0; k < 4; k++) w[k] = (uint64_t)st[2*k] | ((uint64_t)st[2*k+1] << 32);
    u128 initstate = ((u128)w[0] << 64) | (u128)w[1];
    u128 initseq   = ((u128)w[2] << 64) | (u128)w[3];
    g.state = 0; g.inc = (initseq << 1) | (u128)1;
    step(g);
    g.state += initstate;
    step(g);
    g.has32 = 0; g.cache = 0;
}
static inline uint64_t bounded(PCG& g, uint64_t rngv) {
    if (rngv == 0) return 0;
    uint32_t rng = (uint32_t)rngv;
    uint32_t rng_excl = rng + 1u;
    uint64_t m = (uint64_t)next32(g) * (uint64_t)rng_excl;
    uint32_t leftover = (uint32_t)m;
    if (leftover < rng_excl) {
        uint32_t threshold = (uint32_t)((0xFFFFFFFFu - rng) % rng_excl);
        while (leftover < threshold) {
            m = (uint64_t)next32(g) * (uint64_t)rng_excl;
            leftover = (uint32_t)m;
        }
    }
    return m >> 32;
}
static void choice(PCG& g, int pop, int k, int* out) {
    int cnt = 0;
    for (int j = pop - k; j < pop; j++) {
        uint64_t val = bounded(g, (uint64_t)j);
        bool dup = false;
        for (int q = 0; q < cnt; q++) if ((uint64_t)out[q] == val) dup = true;
        out[cnt++] = dup ? j : (int)val;
    }
    for (int i = k - 1; i >= 1; i--) {
        int j = (int)bounded(g, (uint64_t)i);
        int t = out[i]; out[i] = out[j]; out[j] = t;
    }
}
} // namespace rng42

static void build_graph(unsigned in_mask[NN], unsigned out_mask[NN]) {
    rng42::PCG g; rng42::init(g);
    for (int i = 0; i < NN; i++) { in_mask[i] = 0u; out_mask[i] = 0u; }
    for (int i = 1; i < NN; i++) {
        in_mask[i] |= 1u << (i - 1);
        int k = (i < 3) ? i : 3;
        int pick[3];
        rng42::choice(g, i, k, pick);
        for (int q = 0; q < k; q++) in_mask[i] |= 1u << pick[q];
    }
    for (int j = 0; j < NN; j++) {
        unsigned m = in_mask[j];
        while (m) { int s = __builtin_ctz(m); m &= m - 1; out_mask[s] |= 1u << j; }
    }
}

// ===================================================================================
//                                      kernels
// ===================================================================================

__device__ __forceinline__ void fma2(unsigned long long& acc, unsigned long long v2,
                                     unsigned long long w2) {
    asm("fma.rn.f32x2 %0, %1, %2, %0;" : "+l"(acc) : "l"(v2), "l"(w2));
}
__device__ __forceinline__ unsigned long long dup2(float v) {
    unsigned long long r;
    asm("mov.b64 %0, {%1, %1};" : "=l"(r) : "f"(v));
    return r;
}

// pooled mean of x: one block per (b,c)
__global__ __launch_bounds__(128) void pool_x_kernel(const float* __restrict__ x) {
    int bc = blockIdx.x;
    int t = threadIdx.x;
    const float* p = x + (size_t)bc * HW;
    float s = 0.f;
    #pragma unroll
    for (int i = 0; i < 8; i++) s += p[t + i * 128];
    #pragma unroll
    for (int o = 16; o; o >>= 1) s += __shfl_down_sync(FULLM, s, o);
    __shared__ float red[4];
    if ((t & 31) == 0) red[t >> 5] = s;
    __syncthreads();
    if (t == 0) d_pooled[bc] = (red[0] + red[1] + red[2] + red[3]) * (1.f / 1024.f);
}

// weighted aggregation: g_aggr (or d_out) = sum_src d_w[src][b] * node_out[src]
struct AggrP { int nsrc; int src[8]; };
__global__ __launch_bounds__(256) void aggr_kernel(AggrP p, const float* __restrict__ x,
                                                   float* __restrict__ fin, int use_fin) {
    int i = blockIdx.x * 256 + threadIdx.x;     // float4 index
    int b = i >> 14;
    float4 a = make_float4(0.f, 0.f, 0.f, 0.f);
    #pragma unroll 1
    for (int s = 0; s < p.nsrc; s++) {
        int src = p.src[s];
        float w = d_w[src * BB + b];
        const float4* sp4 = (src == 0) ? (const float4*)x
                                       : (const float4*)(&g_node_out[src - 1][0]);
        float4 v = sp4[i];
        a.x = fmaf(w, v.x, a.x); a.y = fmaf(w, v.y, a.y);
        a.z = fmaf(w, v.z, a.z); a.w = fmaf(w, v.w, a.w);
    }
    float4* o = use_fin ? (float4*)fin : (float4*)g_aggr;
    o[i] = a;
}

// 3x3 SAME conv 64->64 on g_aggr + ReLU + pooled mean
// block = (b, co-group of 8), full 32-row image, 256 threads / 8 warps.
// thread: x-quad q = tid&7 (cols 4q..4q+3), row rw = tid>>3; 4 px x 4 co-pairs.
// grid = 32 * 8 = 256.
#define SW 40   // padded smem row width (floats); image col x at index 4+x
__global__ __launch_bounds__(256, 2) void conv_kernel(const float* __restrict__ cw, int nid) {
    __shared__ __align__(16) float s_in[8][34][SW];   // 43.5 KB
    __shared__ __align__(16) float s_w[8][9][8];      // 2.3 KB
    __shared__ float s_red[8][8];
    int tid = threadIdx.x;
    int tx = tid & 31, ty = tid >> 5;       // loader coords (warp ty)
    int q = tid & 7, rw = tid >> 3;         // compute coords
    int b      = blockIdx.x >> 3;
    int cobase = (blockIdx.x & 7) << 3;
    const float* inb = g_aggr + (size_t)b * IMG;

    // zero the two live halo columns (x=-1 -> idx 3, x=32 -> idx 36)
    #pragma unroll 1
    for (int idx = tid; idx < 8 * 34; idx += 256) {
        int ci = idx / 34, r = idx - ci * 34;
        s_in[ci][r][3]  = 0.f;
        s_in[ci][r][36] = 0.f;
    }

    unsigned long long acc2[4][4];          // [px][copair]
    #pragma unroll
    for (int i = 0; i < 4; i++)
        #pragma unroll
        for (int c = 0; c < 4; c++) acc2[i][c] = 0ull;

    #pragma unroll 1
    for (int cc = 0; cc < 8; cc++) {
        int cib = cc * 8;
        // warp ty loads ci slot ty: 34 rows, fully coalesced
        {
            const float* src = inb + (size_t)(cib + ty) * HW;
            #pragma unroll
            for (int r = 0; r < 34; r++) {
                int gy = r - 1;
                float v = ((unsigned)gy < 32u) ? src[gy * 32 + tx] : 0.f;
                s_in[ty][r][4 + tx] = v;
            }
        }
        // weights: cw (node, co, ci, 3, 3) -> s_w[ci][k][co], 576 floats
        #pragma unroll
        for (int it = 0; it < 3; it++) {
            int idx = tid + it * 256;
            if (idx < 576) {
                int co = idx & 7; int r = idx >> 3;
                int ci = r / 9;   int k = r - ci * 9;
                s_w[ci][k][co] =
                    cw[(((size_t)nid * 64 + (cobase + co)) * 64 + (cib + ci)) * 9 + k];
            }
        }
        __syncthreads();
        #pragma unroll 1
        for (int ci = 0; ci < 8; ci++) {
            #pragma unroll
            for (int ky = 0; ky < 3; ky++) {
                const float* row = &s_in[ci][rw + ky][0];
                float f0 = row[3 + 4 * q];
                float4 fm = *reinterpret_cast<const float4*>(&row[4 + 4 * q]);
                float f5 = row[8 + 4 * q];
                unsigned long long v2[6];
                v2[0] = dup2(f0);   v2[1] = dup2(fm.x);
                v2[2] = dup2(fm.y); v2[3] = dup2(fm.z);
                v2[4] = dup2(fm.w); v2[5] = dup2(f5);
                #pragma unroll
                for (int kx = 0; kx < 3; kx++) {
                    const ulonglong2* wp =
                        reinterpret_cast<const ulonglong2*>(&s_w[ci][ky * 3 + kx][0]);
                    ulonglong2 wa = wp[0], wb = wp[1];
                    #pragma unroll
                    for (int i = 0; i < 4; i++) {
                        unsigned long long v = v2[i + kx];
                        fma2(acc2[i][0], v, wa.x);
                        fma2(acc2[i][1], v, wa.y);
                        fma2(acc2[i][2], v, wb.x);
                        fma2(acc2[i][3], v, wb.y);
                    }
                }
            }
        }
        __syncthreads();
    }

    // epilogue: ReLU + float4 store + pooled mean
    float* outb = &g_node_out[nid - 1][(size_t)b * IMG];
    float psum[8];
    #pragma unroll
    for (int c = 0; c < 8; c++) psum[c] = 0.f;
    #pragma unroll
    for (int c = 0; c < 8; c++) {
        int qp = c >> 1, hiSel = c & 1;
        float vals[4];
        #pragma unroll
        for (int i = 0; i < 4; i++) {
            float lo, hi;
            asm("mov.b64 {%0, %1}, %2;" : "=f"(lo), "=f"(hi) : "l"(acc2[i][qp]));
            vals[i] = fmaxf(hiSel ? hi : lo, 0.f);
        }
        float4 o = make_float4(vals[0], vals[1], vals[2], vals[3]);
        *reinterpret_cast<float4*>(&outb[(size_t)(cobase + c) * HW + rw * 32 + 4 * q]) = o;
        psum[c] = (vals[0] + vals[1]) + (vals[2] + vals[3]);
    }
    #pragma unroll
    for (int c = 0; c < 8; c++) {
        #pragma unroll
        for (int o = 16; o; o >>= 1)
            psum[c] += __shfl_down_sync(FULLM, psum[c], o);
    }
    if (tx == 0) {
        #pragma unroll
        for (int c = 0; c < 8; c++) s_red[ty][c] = psum[c];
    }
    __syncthreads();
    if (tid < 8) {
        float s = 0.f;
        #pragma unroll
        for (int wy = 0; wy < 8; wy++) s += s_red[wy][tid];
        d_pooled[b * CC + cobase + tid] = s * (1.f / 1024.f);
    }
}

// attention + cut + bookkeeping. One WARP per batch (grid=32, block=32), lane = node.
struct SP {
    int stage, ntars, nxt;
    int tars[32];
    unsigned attn_before, attn_after;
    unsigned in_mask[NN];
};
__global__ __launch_bounds__(32) void scalar_kernel(SP p, const float* __restrict__ embs,
                                                    const float* __restrict__ W) {
    int b = blockIdx.x;
    int l = threadIdx.x;
    int stage = p.stage;
    int ntars = p.ntars;

    // pooled vector, distributed 2 per lane, broadcast via shfl
    float pc0 = d_pooled[b * CC + l];
    float pc1 = d_pooled[b * CC + 32 + l];

    // q[e] = sum_c pooled[c] * W[c][e], lane holds e = l + {0,32,64,96}
    float q0 = 0.f, q1 = 0.f, q2 = 0.f, q3 = 0.f;
    #pragma unroll
    for (int c = 0; c < CC; c++) {
        float pv = (c < 32) ? __shfl_sync(FULLM, pc0, c)
                            : __shfl_sync(FULLM, pc1, c - 32);
        const float* wr = W + c * EMBD + l;
        q0 = fmaf(pv, wr[0],  q0);
        q1 = fmaf(pv, wr[32], q1);
        q2 = fmaf(pv, wr[64], q2);
        q3 = fmaf(pv, wr[96], q3);
    }
    // logits: lane j ends up holding lg for target j
    float lgj = 0.f;
    #pragma unroll 1
    for (int j = 0; j < ntars; j++) {
        const float* er = embs + p.tars[j] * EMBD + l;
        float s = q0 * er[0] + q1 * er[32] + q2 * er[64] + q3 * er[96];
        #pragma unroll
        for (int o = 16; o; o >>= 1) s += __shfl_down_sync(FULLM, s, o);
        s = __shfl_sync(FULLM, s, 0);
        if (l == j) lgj = s;
    }
    bool isT = (l < ntars);

    // softmax over targets (warp-parallel)
    float v = isT ? lgj : -1e30f;
    #pragma unroll
    for (int o = 16; o; o >>= 1) v = fmaxf(v, __shfl_xor_sync(FULLM, v, o));
    float e = isT ? expf(lgj - v) : 0.f;
    float den = e;
    #pragma unroll
    for (int o = 16; o; o >>= 1) den += __shfl_xor_sync(FULLM, den, o);
    float sa = 1.f, pmv = 1.f;
    if (stage > 0) {
        sa  = d_nattn[stage * BB + b];
        pmv = d_part[stage * BB + b] ? 1.f : 0.f;
    }
    float asj = isT ? (e / den) * sa * pmv : 0.f;     // a_sent[j] on lane j

    // attention distribution: lane owns t = l
    float adv;
    if (stage == 0) adv = 0.f;
    else { adv = d_ad[b * NN + l]; if (l == stage) adv = 0.f; }
    #pragma unroll 1
    for (int j = 0; j < ntars; j++) {
        float aj = __shfl_sync(FULLM, asj, j);
        if (l == p.tars[j]) adv += aj;
    }

    // top-8 (ties -> lowest index): 8 warp argmax rounds
    bool sel = false;
    #pragma unroll 1
    for (int k = 0; k < ATT_KK; k++) {
        float cv = sel ? -1e30f : adv;
        int   ci_ = l;
        #pragma unroll
        for (int o = 16; o; o >>= 1) {
            float ov = __shfl_xor_sync(FULLM, cv, o);
            int   oi = __shfl_xor_sync(FULLM, ci_, o);
            if (ov > cv || (ov == cv && oi < ci_)) { cv = ov; ci_ = oi; }
        }
        if (l == ci_) sel = true;
    }
    float mskv = (sel && adv > ATT_EPSF) ? 1.f : 0.f;
    float ssum = mskv * adv;
    #pragma unroll
    for (int o = 16; o; o >>= 1) ssum += __shfl_xor_sync(FULLM, ssum, o);
    float scale = (ssum > 0.f) ? 1.f / fmaxf(ssum, 1e-12f) : 0.f;
    d_ad[b * NN + l] = adv * mskv * scale;

    // bookkeeping
    if (stage == 0) {
        if (l == 0) d_part[0 * BB + b] = 1;
        int tt = p.tars[isT ? l : 0];
        float mt = __shfl_sync(FULLM, mskv, tt);
        if (isT) {
            float ar = asj * mt * scale;
            d_trans_a[(tt * NN + 0) * BB + b]  = ar;
            d_trans_nf[(tt * NN + 0) * BB + b] = 1.f;
            d_nattn[tt * BB + b] = ar;
        }
    } else {
        if (isT) {
            int t = p.tars[l];
            d_trans_a[(t * NN + stage) * BB + b]  = asj;
            d_trans_nf[(t * NN + stage) * BB + b] = 1.f;
            float prev = ((p.attn_before >> t) & 1u) ? d_nattn[t * BB + b] : 0.f;
            d_nattn[t * BB + b] = prev + asj;
        }
        __syncwarp();
        // renorm (lane t = l handles its own sources in parallel)
        if (l > stage && ((p.attn_after >> l) & 1u)) {
            float nf = mskv * scale;
            unsigned sm = p.in_mask[l] & ((1u << (stage + 1)) - 1u);
            while (sm) {
                int src = __ffs(sm) - 1; sm &= sm - 1;
                d_trans_nf[(l * NN + src) * BB + b] *= nf;
            }
            d_nattn[l * BB + b] *= nf;
        }
    }
    __syncwarp();
    // precompute next node's aggregation weights + part (lane = source id)
    {
        int nx = p.nxt;
        int cm = 0;
        if ((p.in_mask[nx] >> l) & 1u) {
            float tra = d_trans_a[(nx * NN + l) * BB + b] *
                        d_trans_nf[(nx * NN + l) * BB + b];
            int ps = (l == 0) ? 1 : d_part[l * BB + b];
            cm = (tra != 0.f) && ps;
            float wsrc = (l == 0) ? 1.f : d_nattn[l * BB + b];
            d_w[l * BB + b] = cm ? wsrc : 0.f;
        }
        unsigned bal = __ballot_sync(FULLM, cm);
        if (l == 0) d_part[nx * BB + b] = (bal != 0u);
    }
}

// ===================================================================================
//                                     launcher
// ===================================================================================
extern "C" void kernel_launch(void* const* d_in, const int* in_sizes, int n_in,
                              void* d_out, int out_size) {
    const float* x    = (const float*)d_in[0];
    const float* embs = (const float*)d_in[1];
    const float* w1   = (const float*)d_in[2];
    const float* w2   = (const float*)d_in[3];
    const float* cw   = (const float*)d_in[4];
    float* outp = (float*)d_out;
    (void)in_sizes; (void)n_in; (void)out_size;

    unsigned in_mask[NN], out_mask[NN];
    build_graph(in_mask, out_mask);

    pool_x_kernel<<<BB * CC, 128>>>(x);

    unsigned attn = 0u;
    // stage 0
    {
        SP sp;
        sp.stage = 0; sp.nxt = 1; sp.ntars = 0;
        unsigned m = out_mask[0];
        while (m) { int t = __builtin_ctz(m); m &= m - 1; sp.tars[sp.ntars++] = t; }
        for (int t = sp.ntars; t < 32; t++) sp.tars[t] = 0;
        sp.attn_before = 0u; sp.attn_after = out_mask[0];
        for (int t = 0; t < NN; t++) sp.in_mask[t] = in_mask[t];
        scalar_kernel<<<BB, 32>>>(sp, embs, w1);
        attn |= out_mask[0];
    }
    for (int nid = 1; nid < NN - 1; nid++) {
        AggrP ap; ap.nsrc = 0;
        unsigned m = in_mask[nid];
        while (m) { int s = __builtin_ctz(m); m &= m - 1; ap.src[ap.nsrc++] = s; }
        for (int s = ap.nsrc; s < 8; s++) ap.src[s] = 0;
        aggr_kernel<<<TOT / 1024, 256>>>(ap, x, outp, 0);

        conv_kernel<<<BB * 8, 256>>>(cw, nid);

        SP sp;
        sp.stage = nid; sp.nxt = nid + 1; sp.ntars = 0;
        unsigned mm = out_mask[nid];
        while (mm) { int t = __builtin_ctz(mm); mm &= mm - 1; sp.tars[sp.ntars++] = t; }
        for (int t = sp.ntars; t < 32; t++) sp.tars[t] = 0;
        sp.attn_before = attn; sp.attn_after = attn | out_mask[nid];
        for (int t = 0; t < NN; t++) sp.in_mask[t] = in_mask[t];
        scalar_kernel<<<BB, 32>>>(sp, embs, w2);
        attn |= out_mask[nid];
    }
    // final node 31: aggregation only -> d_out
    {
        AggrP ap; ap.nsrc = 0;
        unsigned m = in_mask[NN - 1];
        while (m) { int s = __builtin_ctz(m); m &= m - 1; ap.src[ap.nsrc++] = s; }
        for (int s = ap.nsrc; s < 8; s++) ap.src[s] = 0;
        aggr_kernel<<<TOT / 1024, 256>>>(ap, x, outp, 1);
    }
}